// round 4
// baseline (speedup 1.0000x reference)
#include <cuda_runtime.h>
#include <cuda_fp16.h>
#include <cstdint>

#define NB    8192
#define SH    136    // padded half stride (68 words -> conflict-free)
#define ZSTH  136    // padded half2 stride for zth pair-rows

// shared memory byte offsets (16B aligned)
#define OFF_XRAW   0        // 2*512*4 = 4096
#define OFF_B1     4096     // 512
#define OFF_B2     4608     // 512
#define OFF_B3     5120     // 128
#define OFF_W3T    5248     // 32*136*2 = 8704
#define OFF_H1     13952    // 128*136*2 = 34816  (W2 staged here in prologue)
#define OFF_H2     48768    // 128*136*2 = 34816
#define OFF_ZTH    83584    // 2 * 16*136*4 = 17408 (double-buffered half2 channel pairs)
#define SMEM_BYTES 100992

#define NTHREADS 320   // 8 producer warps + 2 consumer warps

// named barriers: 1 = producer-internal (256), 2+par = full, 4+par = empty (320)
#define BAR_SYNC(id, n)   asm volatile("bar.sync %0, %1;"   :: "r"(id), "r"(n) : "memory")
#define BAR_ARRIVE(id, n) asm volatile("bar.arrive %0, %1;" :: "r"(id), "r"(n) : "memory")

__device__ __forceinline__ void mma16816(float* d, const uint32_t* a, const uint32_t* b) {
    asm volatile(
        "mma.sync.aligned.m16n8k16.row.col.f32.f16.f16.f32 "
        "{%0,%1,%2,%3},{%4,%5,%6,%7},{%8,%9},{%0,%1,%2,%3};\n"
        : "+f"(d[0]), "+f"(d[1]), "+f"(d[2]), "+f"(d[3])
        : "r"(a[0]), "r"(a[1]), "r"(a[2]), "r"(a[3]), "r"(b[0]), "r"(b[1]));
}

__device__ __forceinline__ void mma16808(float* d, const uint32_t* a, uint32_t b) {
    asm volatile(
        "mma.sync.aligned.m16n8k8.row.col.f32.f16.f16.f32 "
        "{%0,%1,%2,%3},{%4,%5},{%6},{%0,%1,%2,%3};\n"
        : "+f"(d[0]), "+f"(d[1]), "+f"(d[2]), "+f"(d[3])
        : "r"(a[0]), "r"(a[1]), "r"(b));
}

#define LDSM4(r, addr) \
    asm volatile("ldmatrix.sync.aligned.m8n8.x4.shared.b16 {%0,%1,%2,%3}, [%4];" \
                 : "=r"((r)[0]), "=r"((r)[1]), "=r"((r)[2]), "=r"((r)[3]) : "r"(addr))

#define STSM4(addr, r0, r1, r2, r3) \
    asm volatile("stmatrix.sync.aligned.m8n8.x4.shared.b16 [%0], {%1,%2,%3,%4};" \
                 :: "r"(addr), "r"(r0), "r"(r1), "r"(r2), "r"(r3))

__device__ __forceinline__ void cp16(void* s, const void* g) {
    uint32_t sa = (uint32_t)__cvta_generic_to_shared(s);
    asm volatile("cp.async.ca.shared.global [%0], [%1], 16;\n" :: "r"(sa), "l"(g));
}

__device__ __forceinline__ uint32_t packh2(float a, float b) {
    __half2 h = __floats2half2_rn(a, b);
    return *(uint32_t*)&h;
}

__device__ __forceinline__ uint32_t h2max(uint32_t a, uint32_t b) {
    __half2 r = __hmax2(*(__half2*)&a, *(__half2*)&b);
    return *(uint32_t*)&r;
}
__device__ __forceinline__ uint32_t h2min(uint32_t a, uint32_t b) {
    __half2 r = __hmin2(*(__half2*)&a, *(__half2*)&b);
    return *(uint32_t*)&r;
}

#define CEXH(a, b, dsc) do { uint32_t _hi = h2max(a, b), _lo = h2min(a, b); \
                             (a) = (dsc) ? _hi : _lo; (b) = (dsc) ? _lo : _hi; } while (0)

__global__ void __launch_bounds__(NTHREADS, 1)
enc_kernel(const float* __restrict__ x,  const float* __restrict__ W1,
           const float* __restrict__ b1, const float* __restrict__ W2,
           const float* __restrict__ b2, const float* __restrict__ W3,
           const float* __restrict__ b3, const float* __restrict__ pw,
           const float* __restrict__ eps, float* __restrict__ out) {
    extern __shared__ char smem[];
    float*    xraw  = (float*)(smem + OFF_XRAW);
    float*    b1s   = (float*)(smem + OFF_B1);
    float*    b2s   = (float*)(smem + OFF_B2);
    float*    b3s   = (float*)(smem + OFF_B3);
    __half*   W3t   = (__half*)(smem + OFF_W3T);
    __half*   h1    = (__half*)(smem + OFF_H1);
    __half*   h2    = (__half*)(smem + OFF_H2);
    uint32_t* zth   = (uint32_t*)(smem + OFF_ZTH);   // [2][16][ZSTH] half2

    const int tid  = threadIdx.x;
    const int w    = tid >> 5;
    const int lane = tid & 31;
    const int g    = lane >> 2, t = lane & 3;
    const int grid = gridDim.x;

    // producer warp tiles
    const int wm12 = (w & 1) * 64, wn12 = (w >> 1) * 32;   // layers 1,2: 64x32 (warps 0-7)
    const int wm3  = (w & 3) * 32, wn3  = (w >> 2) * 16;   // layer 3: 32x16

    // ldmatrix / stmatrix lane address components
    const int mi    = lane >> 3;
    const int arow  = (mi & 1) * 8 + (lane & 7);
    const int acol  = (mi >> 1) * 8;

    const uint32_t smem_u32 = (uint32_t)__cvta_generic_to_shared(smem);
    const uint32_t aBase2 = smem_u32 + OFF_H1 + ((wm12 + arow) * SH + acol) * 2;
    const uint32_t aBase3 = smem_u32 + OFF_H2 + ((wm3  + arow) * SH + acol) * 2;
    const uint32_t sBase1 = smem_u32 + OFF_H1 + ((wm12 + arow) * SH + wn12 + acol) * 2;
    const uint32_t sBase2 = smem_u32 + OFF_H2 + ((wm12 + arow) * SH + wn12 + acol) * 2;

    // ---------------- prologue (all 320 threads) ----------------
    __half* W2t = h1;  // stage W2 in h1 region
    for (int i = tid; i < 16384; i += NTHREADS) {   // W2t[n][k] = W2[k][n]
        int k = i >> 7, n = i & 127;
        W2t[n * SH + k] = __float2half(W2[i]);
    }
    for (int i = tid; i < 4096; i += NTHREADS) {    // W3t[n][k] = W3[k][n]
        int k = i >> 5, n = i & 31;
        W3t[n * SH + k] = __float2half(W3[i]);
    }
    if (tid < 128) { b1s[tid] = b1[tid]; b2s[tid] = b2[tid]; }
    else if (tid >= 160 && tid < 192) b3s[tid - 160] = b3[tid - 160];
    __syncthreads();

    if (w < 8) {
        // ================= PRODUCER (8 warps, 256 threads) =================
        uint32_t bW2[4][16];
#pragma unroll
        for (int nt = 0; nt < 4; nt++) {
            const __half* bp = W2t + (wn12 + 8 * nt + g) * SH + 2 * t;
#pragma unroll
            for (int ks = 0; ks < 8; ks++) {
                bW2[nt][2 * ks]     = *(const uint32_t*)(bp + 16 * ks);
                bW2[nt][2 * ks + 1] = *(const uint32_t*)(bp + 16 * ks + 8);
            }
        }
        uint32_t bW1[4];
#pragma unroll
        for (int nt = 0; nt < 4; nt++) {
            int n = wn12 + 8 * nt + g;
            bW1[nt] = (t < 2) ? packh2(W1[(2 * t) * 128 + n], W1[(2 * t + 1) * 128 + n]) : 0u;
        }

        // prefetch first batch
        if (tid < 128) cp16(xraw + tid * 4, x + (size_t)blockIdx.x * 512 + tid * 4);
        asm volatile("cp.async.commit_group;\n");

        int buf = 0, par = 0;
        for (int b = blockIdx.x; b < NB; b += grid) {
            int bn = b + grid; if (bn >= NB) bn = blockIdx.x;
            if (tid < 128) cp16(xraw + (buf ^ 1) * 512 + tid * 4, x + (size_t)bn * 512 + tid * 4);
            asm volatile("cp.async.commit_group;\n");
            asm volatile("cp.async.wait_group 1;\n");
            BAR_SYNC(1, 256);

            float acc[64];

            // ---- layer 1 ----
#pragma unroll
            for (int i = 0; i < 64; i++) acc[i] = 0.f;
            {
                uint32_t a1[4][2];
#pragma unroll
                for (int ms = 0; ms < 4; ms++) {
                    int row = wm12 + 16 * ms + g;
                    if (t < 2) {
                        float2 v0 = *(const float2*)&xraw[buf * 512 + row * 4 + 2 * t];
                        float2 v1 = *(const float2*)&xraw[buf * 512 + (row + 8) * 4 + 2 * t];
                        a1[ms][0] = packh2(v0.x, v0.y);
                        a1[ms][1] = packh2(v1.x, v1.y);
                    } else { a1[ms][0] = 0u; a1[ms][1] = 0u; }
                }
#pragma unroll
                for (int ms = 0; ms < 4; ms++)
#pragma unroll
                    for (int nt = 0; nt < 4; nt++)
                        mma16808(&acc[(ms * 4 + nt) * 4], a1[ms], bW1[nt]);
#pragma unroll
                for (int ms = 0; ms < 4; ms++)
#pragma unroll
                    for (int nh = 0; nh < 2; nh++) {
                        int c0 = wn12 + 16 * nh + 2 * t;
                        float bb0 = b1s[c0], bb1 = b1s[c0 + 1];
                        float bb2 = b1s[c0 + 8], bb3 = b1s[c0 + 9];
                        float* aA = &acc[(ms * 4 + 2 * nh) * 4];
                        float* aB = &acc[(ms * 4 + 2 * nh + 1) * 4];
                        uint32_t p0 = packh2(fmaxf(aA[0] + bb0, 0.f), fmaxf(aA[1] + bb1, 0.f));
                        uint32_t p1 = packh2(fmaxf(aA[2] + bb0, 0.f), fmaxf(aA[3] + bb1, 0.f));
                        uint32_t p2 = packh2(fmaxf(aB[0] + bb2, 0.f), fmaxf(aB[1] + bb3, 0.f));
                        uint32_t p3 = packh2(fmaxf(aB[2] + bb2, 0.f), fmaxf(aB[3] + bb3, 0.f));
                        STSM4(sBase1 + (16 * ms * SH + 16 * nh) * 2, p0, p1, p2, p3);
                    }
            }
            BAR_SYNC(1, 256);

            // ---- layer 2 (B in registers) ----
#pragma unroll
            for (int i = 0; i < 64; i++) acc[i] = 0.f;
            {
                uint32_t af[2][4][4];
#pragma unroll
                for (int ms = 0; ms < 4; ms++) LDSM4(af[0][ms], aBase2 + (16 * ms * SH) * 2);
#pragma unroll
                for (int ks = 0; ks < 8; ks++) {
                    if (ks < 7) {
#pragma unroll
                        for (int ms = 0; ms < 4; ms++)
                            LDSM4(af[(ks + 1) & 1][ms], aBase2 + (16 * ms * SH + 16 * (ks + 1)) * 2);
                    }
#pragma unroll
                    for (int ms = 0; ms < 4; ms++)
#pragma unroll
                        for (int nt = 0; nt < 4; nt++)
                            mma16816(&acc[(ms * 4 + nt) * 4], af[ks & 1][ms], &bW2[nt][2 * ks]);
                }
#pragma unroll
                for (int ms = 0; ms < 4; ms++)
#pragma unroll
                    for (int nh = 0; nh < 2; nh++) {
                        int c0 = wn12 + 16 * nh + 2 * t;
                        float bb0 = b2s[c0], bb1 = b2s[c0 + 1];
                        float bb2 = b2s[c0 + 8], bb3 = b2s[c0 + 9];
                        float* aA = &acc[(ms * 4 + 2 * nh) * 4];
                        float* aB = &acc[(ms * 4 + 2 * nh + 1) * 4];
                        uint32_t p0 = packh2(fmaxf(aA[0] + bb0, 0.f), fmaxf(aA[1] + bb1, 0.f));
                        uint32_t p1 = packh2(fmaxf(aA[2] + bb0, 0.f), fmaxf(aA[3] + bb1, 0.f));
                        uint32_t p2 = packh2(fmaxf(aB[0] + bb2, 0.f), fmaxf(aB[1] + bb3, 0.f));
                        uint32_t p3 = packh2(fmaxf(aB[2] + bb2, 0.f), fmaxf(aB[3] + bb3, 0.f));
                        STSM4(sBase2 + (16 * ms * SH + 16 * nh) * 2, p0, p1, p2, p3);
                    }
            }
            BAR_SYNC(1, 256);

            // ---- layer 3 -> zth[par] ----
            {
                float acc3[16];
#pragma unroll
                for (int i = 0; i < 16; i++) acc3[i] = 0.f;
#pragma unroll
                for (int ks = 0; ks < 8; ks++) {
                    uint32_t a3[2][4], bf[2][2];
#pragma unroll
                    for (int ms = 0; ms < 2; ms++)
                        LDSM4(a3[ms], aBase3 + (16 * ms * SH + 16 * ks) * 2);
#pragma unroll
                    for (int nt = 0; nt < 2; nt++) {
                        const __half* bp = W3t + (wn3 + 8 * nt + g) * SH + 16 * ks + 2 * t;
                        bf[nt][0] = *(const uint32_t*)(bp);
                        bf[nt][1] = *(const uint32_t*)(bp + 8);
                    }
#pragma unroll
                    for (int ms = 0; ms < 2; ms++)
#pragma unroll
                        for (int nt = 0; nt < 2; nt++)
                            mma16816(&acc3[(ms * 2 + nt) * 4], a3[ms], bf[nt]);
                }
                // wait for consumer to release this buffer, then store
                BAR_SYNC(4 + par, NTHREADS);
                uint32_t* ztp = zth + par * (16 * ZSTH);
#pragma unroll
                for (int ms = 0; ms < 2; ms++)
#pragma unroll
                    for (int nt = 0; nt < 2; nt++) {
                        int r  = wm3 + 16 * ms + g;
                        int c  = wn3 + 8 * nt + 2 * t;
                        int cp = c >> 1;
                        float* a = &acc3[(ms * 2 + nt) * 4];
                        float bb0 = b3s[c], bb1 = b3s[c + 1];
                        ztp[cp * ZSTH + r]     = packh2(a[0] + bb0, a[1] + bb1);
                        ztp[cp * ZSTH + r + 8] = packh2(a[2] + bb0, a[3] + bb1);
                    }
                BAR_ARRIVE(2 + par, NTHREADS);   // zth[par] full
            }
            buf ^= 1; par ^= 1;
        }
    } else {
        // ================= CONSUMER (2 warps, 64 threads) =================
        const int ws = w - 8;   // 0 or 1: latents 8*ws .. 8*ws+7

        // FSPool weights: stream ci -> channels (c0, c0+1), c0 = 2*(8*ws+ci)
        float wlo[8][4], whi[8][4];
#pragma unroll
        for (int ci = 0; ci < 8; ci++) {
            int c0 = 2 * (8 * ws + ci);
#pragma unroll
            for (int j = 0; j < 4; j++) {
                int p = 4 * lane + j;
                float pos = (float)p * (20.0f / 127.0f);
                int idx = (int)pos; if (idx > 20) idx = 20;
                float frac = pos - (float)idx;
                int idx2 = idx + 1; if (idx2 > 20) idx2 = 20;
                wlo[ci][j] = (1.0f - frac) * pw[c0 * 21 + idx]       + frac * pw[c0 * 21 + idx2];
                whi[ci][j] = (1.0f - frac) * pw[(c0 + 1) * 21 + idx] + frac * pw[(c0 + 1) * 21 + idx2];
            }
        }

        // prime both empty parities
        BAR_ARRIVE(4, NTHREADS);
        BAR_ARRIVE(5, NTHREADS);

        int par = 0;
        for (int b = blockIdx.x; b < NB; b += grid) {
            // prefetch eps (latency overlapped with full-wait)
            float ev = 0.f;
            if (lane < 8) ev = eps[(size_t)b * 16 + 8 * ws + lane];

            BAR_SYNC(2 + par, NTHREADS);         // wait zth[par] full
            const uint32_t* ztp = zth + par * (16 * ZSTH);
            uint32_t v[8][4];
#pragma unroll
            for (int ci = 0; ci < 8; ci++) {
                uint4 q = *(const uint4*)&ztp[(8 * ws + ci) * ZSTH + 4 * lane];
                v[ci][0] = q.x; v[ci][1] = q.y; v[ci][2] = q.z; v[ci][3] = q.w;
            }
            BAR_ARRIVE(4 + par, NTHREADS);       // buffer consumed

            // bitonic sort (descending), element e = 4*lane + j, 8 half2 streams
#pragma unroll
            for (int ci = 0; ci < 8; ci++) { CEXH(v[ci][0], v[ci][1], true); CEXH(v[ci][2], v[ci][3], false); }
            {
                const bool dsc = (lane & 1) == 0;
#pragma unroll
                for (int ci = 0; ci < 8; ci++) { CEXH(v[ci][0], v[ci][2], dsc); CEXH(v[ci][1], v[ci][3], dsc); }
#pragma unroll
                for (int ci = 0; ci < 8; ci++) { CEXH(v[ci][0], v[ci][1], dsc); CEXH(v[ci][2], v[ci][3], dsc); }
            }
#pragma unroll
            for (int kk = 8; kk <= 128; kk <<= 1) {
                const bool dsc = (lane & (kk >> 2)) == 0;
#pragma unroll
                for (int d = kk >> 1; d >= 4; d >>= 1) {
                    const bool keep = dsc == ((lane & (d >> 2)) == 0);
#pragma unroll
                    for (int ci = 0; ci < 8; ci++)
#pragma unroll
                        for (int j = 0; j < 4; j++) {
                            uint32_t p = __shfl_xor_sync(0xffffffffu, v[ci][j], d >> 2);
                            v[ci][j] = keep ? h2max(v[ci][j], p) : h2min(v[ci][j], p);
                        }
                }
#pragma unroll
                for (int ci = 0; ci < 8; ci++) { CEXH(v[ci][0], v[ci][2], dsc); CEXH(v[ci][1], v[ci][3], dsc); }
#pragma unroll
                for (int ci = 0; ci < 8; ci++) { CEXH(v[ci][0], v[ci][1], dsc); CEXH(v[ci][2], v[ci][3], dsc); }
            }

            // weighted pool; stream ci = latent 8*ws+ci: lo->mu, hi->logvar
            float s[16];
#pragma unroll
            for (int ci = 0; ci < 8; ci++) {
                float slo = 0.f, shi = 0.f;
#pragma unroll
                for (int j = 0; j < 4; j++) {
                    float2 f = __half22float2(*(__half2*)&v[ci][j]);
                    slo += f.x * wlo[ci][j];
                    shi += f.y * whi[ci][j];
                }
                s[2 * ci] = slo; s[2 * ci + 1] = shi;
            }
#pragma unroll
            for (int off = 16; off > 0; off >>= 1)
#pragma unroll
                for (int i = 0; i < 16; i++)
                    s[i] += __shfl_xor_sync(0xffffffffu, s[i], off);

            if (lane < 8) {
                const int l = 8 * ws + lane;
                float mu = s[2 * lane];
                float lv = s[2 * lane + 1];
                float sp = mu + ev * expf(0.5f * lv);
                out[(size_t)b * 16 + l]                       = mu;
                out[(size_t)NB * 16 + (size_t)b * 16 + l]     = lv;
                out[(size_t)2 * NB * 16 + (size_t)b * 16 + l] = sp;
            }
            par ^= 1;
        }
    }
}

extern "C" void kernel_launch(void* const* d_in, const int* in_sizes, int n_in,
                              void* d_out, int out_size) {
    const float* x   = (const float*)d_in[0];
    const float* W1  = (const float*)d_in[1];
    const float* b1  = (const float*)d_in[2];
    const float* W2  = (const float*)d_in[3];
    const float* b2  = (const float*)d_in[4];
    const float* W3  = (const float*)d_in[5];
    const float* b3  = (const float*)d_in[6];
    const float* pw  = (const float*)d_in[7];
    const float* eps = (const float*)d_in[8];
    float* out = (float*)d_out;

    int dev = 0;
    cudaGetDevice(&dev);
    int nsm = 148;
    cudaDeviceGetAttribute(&nsm, cudaDevAttrMultiProcessorCount, dev);
    cudaFuncSetAttribute(enc_kernel, cudaFuncAttributeMaxDynamicSharedMemorySize, SMEM_BYTES);
    enc_kernel<<<nsm, NTHREADS, SMEM_BYTES>>>(x, W1, b1, W2, b2, W3, b3, pw, eps, out);
}

// round 6
// speedup vs baseline: 2.0760x; 2.0760x over previous
#include <cuda_runtime.h>
#include <cuda_fp16.h>
#include <cstdint>

#define NB    8192
#define SH    136    // padded half stride (68 words -> conflict-free)
#define ZSTH  136    // padded half2 stride for zth pair-rows

// shared memory byte offsets (16B aligned)
#define OFF_XRAW   0        // 4*512*4 = 8192 (4-slot ring)
#define OFF_B1     8192     // 512
#define OFF_B2     8704     // 512
#define OFF_B3     9216     // 128
#define OFF_W3T    9344     // 32*136*2 = 8704
#define OFF_H1     18048    // 128*136*2 = 34816  (W2 staged here in prologue)
#define OFF_H2     52864    // 128*136*2 = 34816
#define OFF_ZTH    87680    // 2*16*136*4 = 17408 (one buffer per batch of the pair)
#define SMEM_BYTES 105088

__device__ __forceinline__ void mma16816(float* d, const uint32_t* a, const uint32_t* b) {
    asm volatile(
        "mma.sync.aligned.m16n8k16.row.col.f32.f16.f16.f32 "
        "{%0,%1,%2,%3},{%4,%5,%6,%7},{%8,%9},{%0,%1,%2,%3};\n"
        : "+f"(d[0]), "+f"(d[1]), "+f"(d[2]), "+f"(d[3])
        : "r"(a[0]), "r"(a[1]), "r"(a[2]), "r"(a[3]), "r"(b[0]), "r"(b[1]));
}

__device__ __forceinline__ void mma16808(float* d, const uint32_t* a, uint32_t b) {
    asm volatile(
        "mma.sync.aligned.m16n8k8.row.col.f32.f16.f16.f32 "
        "{%0,%1,%2,%3},{%4,%5},{%6},{%0,%1,%2,%3};\n"
        : "+f"(d[0]), "+f"(d[1]), "+f"(d[2]), "+f"(d[3])
        : "r"(a[0]), "r"(a[1]), "r"(b));
}

#define LDSM4(r, addr) \
    asm volatile("ldmatrix.sync.aligned.m8n8.x4.shared.b16 {%0,%1,%2,%3}, [%4];" \
                 : "=r"((r)[0]), "=r"((r)[1]), "=r"((r)[2]), "=r"((r)[3]) : "r"(addr))

#define STSM4(addr, r0, r1, r2, r3) \
    asm volatile("stmatrix.sync.aligned.m8n8.x4.shared.b16 [%0], {%1,%2,%3,%4};" \
                 :: "r"(addr), "r"(r0), "r"(r1), "r"(r2), "r"(r3))

__device__ __forceinline__ void cp16(void* s, const void* g) {
    uint32_t sa = (uint32_t)__cvta_generic_to_shared(s);
    asm volatile("cp.async.ca.shared.global [%0], [%1], 16;\n" :: "r"(sa), "l"(g));
}

__device__ __forceinline__ uint32_t packh2(float a, float b) {
    __half2 h = __floats2half2_rn(a, b);
    return *(uint32_t*)&h;
}

__device__ __forceinline__ uint32_t h2max(uint32_t a, uint32_t b) {
    __half2 r = __hmax2(*(__half2*)&a, *(__half2*)&b);
    return *(uint32_t*)&r;
}
__device__ __forceinline__ uint32_t h2min(uint32_t a, uint32_t b) {
    __half2 r = __hmin2(*(__half2*)&a, *(__half2*)&b);
    return *(uint32_t*)&r;
}

#define CEXH(a, b, dsc) do { uint32_t _hi = h2max(a, b), _lo = h2min(a, b); \
                             (a) = (dsc) ? _hi : _lo; (b) = (dsc) ? _lo : _hi; } while (0)

__global__ void __launch_bounds__(256, 1)
enc_kernel(const float* __restrict__ x,  const float* __restrict__ W1,
           const float* __restrict__ b1, const float* __restrict__ W2,
           const float* __restrict__ b2, const float* __restrict__ W3,
           const float* __restrict__ b3, const float* __restrict__ pw,
           const float* __restrict__ eps, float* __restrict__ out) {
    extern __shared__ char smem[];
    float*    xraw  = (float*)(smem + OFF_XRAW);
    float*    b1s   = (float*)(smem + OFF_B1);
    float*    b2s   = (float*)(smem + OFF_B2);
    float*    b3s   = (float*)(smem + OFF_B3);
    __half*   W3t   = (__half*)(smem + OFF_W3T);
    __half*   h1    = (__half*)(smem + OFF_H1);
    __half*   h2    = (__half*)(smem + OFF_H2);
    uint32_t* zth   = (uint32_t*)(smem + OFF_ZTH);   // [2][16][ZSTH] half2

    const int tid  = threadIdx.x;
    const int w    = tid >> 5;
    const int lane = tid & 31;
    const int g    = lane >> 2, t = lane & 3;
    const int grid = gridDim.x;

    // warp tiles
    const int wm12 = (w & 1) * 64, wn12 = (w >> 1) * 32;   // layers 1,2: 64x32
    const int wm3  = (w & 3) * 32, wn3  = (w >> 2) * 16;   // layer 3: 32x16

    // ldmatrix / stmatrix lane address components
    const int mi    = lane >> 3;
    const int arow  = (mi & 1) * 8 + (lane & 7);
    const int acol  = (mi >> 1) * 8;

    const uint32_t smem_u32 = (uint32_t)__cvta_generic_to_shared(smem);
    const uint32_t aBase2 = smem_u32 + OFF_H1 + ((wm12 + arow) * SH + acol) * 2;
    const uint32_t aBase3 = smem_u32 + OFF_H2 + ((wm3  + arow) * SH + acol) * 2;
    const uint32_t sBase1 = smem_u32 + OFF_H1 + ((wm12 + arow) * SH + wn12 + acol) * 2;
    const uint32_t sBase2 = smem_u32 + OFF_H2 + ((wm12 + arow) * SH + wn12 + acol) * 2;

    // ---------------- prologue ----------------
    __half* W2t = h1;  // stage W2 in h1 region, consumed into registers below
    for (int i = tid; i < 16384; i += 256) {   // W2t[n][k] = W2[k][n]
        int k = i >> 7, n = i & 127;
        W2t[n * SH + k] = __float2half(W2[i]);
    }
    for (int i = tid; i < 4096; i += 256) {    // W3t[n][k] = W3[k][n]
        int k = i >> 5, n = i & 31;
        W3t[n * SH + k] = __float2half(W3[i]);
    }
    if (tid < 128) { b1s[tid] = b1[tid]; b2s[tid] = b2[tid]; }
    if (tid < 32)  b3s[tid] = b3[tid];
    __syncthreads();

    // persistent W2 fragments (64 regs/lane)
    uint32_t bW2[4][16];
#pragma unroll
    for (int nt = 0; nt < 4; nt++) {
        const __half* bp = W2t + (wn12 + 8 * nt + g) * SH + 2 * t;
#pragma unroll
        for (int ks = 0; ks < 8; ks++) {
            bW2[nt][2 * ks]     = *(const uint32_t*)(bp + 16 * ks);
            bW2[nt][2 * ks + 1] = *(const uint32_t*)(bp + 16 * ks + 8);
        }
    }
    // persistent W1 fragments
    uint32_t bW1[4];
#pragma unroll
    for (int nt = 0; nt < 4; nt++) {
        int n = wn12 + 8 * nt + g;
        bW1[nt] = (t < 2) ? packh2(W1[(2 * t) * 128 + n], W1[(2 * t + 1) * 128 + n]) : 0u;
    }
    // FSPool weights: stream parity q -> channels (4w+2q, 4w+2q+1)
    float wlo[2][4], whi[2][4];
#pragma unroll
    for (int q = 0; q < 2; q++) {
        int c0 = 4 * w + 2 * q;
#pragma unroll
        for (int j = 0; j < 4; j++) {
            int p = 4 * lane + j;
            float pos = (float)p * (20.0f / 127.0f);
            int idx = (int)pos; if (idx > 20) idx = 20;
            float frac = pos - (float)idx;
            int idx2 = idx + 1; if (idx2 > 20) idx2 = 20;
            wlo[q][j] = (1.0f - frac) * pw[c0 * 21 + idx]       + frac * pw[c0 * 21 + idx2];
            whi[q][j] = (1.0f - frac) * pw[(c0 + 1) * 21 + idx] + frac * pw[(c0 + 1) * 21 + idx2];
        }
    }

    // one full batch pipeline (layers 1-3), writing z to ztp
    auto run_batch = [&](const float* xb, uint32_t* ztp) {
        float acc[64];
        // ---- layer 1 ----
#pragma unroll
        for (int i = 0; i < 64; i++) acc[i] = 0.f;
        {
            uint32_t a1[4][2];
#pragma unroll
            for (int ms = 0; ms < 4; ms++) {
                int row = wm12 + 16 * ms + g;
                if (t < 2) {
                    float2 v0 = *(const float2*)&xb[row * 4 + 2 * t];
                    float2 v1 = *(const float2*)&xb[(row + 8) * 4 + 2 * t];
                    a1[ms][0] = packh2(v0.x, v0.y);
                    a1[ms][1] = packh2(v1.x, v1.y);
                } else { a1[ms][0] = 0u; a1[ms][1] = 0u; }
            }
#pragma unroll
            for (int ms = 0; ms < 4; ms++)
#pragma unroll
                for (int nt = 0; nt < 4; nt++)
                    mma16808(&acc[(ms * 4 + nt) * 4], a1[ms], bW1[nt]);
#pragma unroll
            for (int ms = 0; ms < 4; ms++)
#pragma unroll
                for (int nh = 0; nh < 2; nh++) {
                    int c0 = wn12 + 16 * nh + 2 * t;
                    float bb0 = b1s[c0], bb1 = b1s[c0 + 1];
                    float bb2 = b1s[c0 + 8], bb3 = b1s[c0 + 9];
                    float* aA = &acc[(ms * 4 + 2 * nh) * 4];
                    float* aB = &acc[(ms * 4 + 2 * nh + 1) * 4];
                    uint32_t p0 = packh2(fmaxf(aA[0] + bb0, 0.f), fmaxf(aA[1] + bb1, 0.f));
                    uint32_t p1 = packh2(fmaxf(aA[2] + bb0, 0.f), fmaxf(aA[3] + bb1, 0.f));
                    uint32_t p2 = packh2(fmaxf(aB[0] + bb2, 0.f), fmaxf(aB[1] + bb3, 0.f));
                    uint32_t p3 = packh2(fmaxf(aB[2] + bb2, 0.f), fmaxf(aB[3] + bb3, 0.f));
                    STSM4(sBase1 + (16 * ms * SH + 16 * nh) * 2, p0, p1, p2, p3);
                }
        }
        __syncthreads();

        // ---- layer 2 (B in registers) ----
#pragma unroll
        for (int i = 0; i < 64; i++) acc[i] = 0.f;
        {
            uint32_t af[2][4][4];
#pragma unroll
            for (int ms = 0; ms < 4; ms++) LDSM4(af[0][ms], aBase2 + (16 * ms * SH) * 2);
#pragma unroll
            for (int ks = 0; ks < 8; ks++) {
                if (ks < 7) {
#pragma unroll
                    for (int ms = 0; ms < 4; ms++)
                        LDSM4(af[(ks + 1) & 1][ms], aBase2 + (16 * ms * SH + 16 * (ks + 1)) * 2);
                }
#pragma unroll
                for (int ms = 0; ms < 4; ms++)
#pragma unroll
                    for (int nt = 0; nt < 4; nt++)
                        mma16816(&acc[(ms * 4 + nt) * 4], af[ks & 1][ms], &bW2[nt][2 * ks]);
            }
#pragma unroll
            for (int ms = 0; ms < 4; ms++)
#pragma unroll
                for (int nh = 0; nh < 2; nh++) {
                    int c0 = wn12 + 16 * nh + 2 * t;
                    float bb0 = b2s[c0], bb1 = b2s[c0 + 1];
                    float bb2 = b2s[c0 + 8], bb3 = b2s[c0 + 9];
                    float* aA = &acc[(ms * 4 + 2 * nh) * 4];
                    float* aB = &acc[(ms * 4 + 2 * nh + 1) * 4];
                    uint32_t p0 = packh2(fmaxf(aA[0] + bb0, 0.f), fmaxf(aA[1] + bb1, 0.f));
                    uint32_t p1 = packh2(fmaxf(aA[2] + bb0, 0.f), fmaxf(aA[3] + bb1, 0.f));
                    uint32_t p2 = packh2(fmaxf(aB[0] + bb2, 0.f), fmaxf(aB[1] + bb3, 0.f));
                    uint32_t p3 = packh2(fmaxf(aB[2] + bb2, 0.f), fmaxf(aB[3] + bb3, 0.f));
                    STSM4(sBase2 + (16 * ms * SH + 16 * nh) * 2, p0, p1, p2, p3);
                }
        }
        __syncthreads();

        // ---- layer 3 -> ztp (half2 channel pairs) ----
        {
            float acc3[16];
#pragma unroll
            for (int i = 0; i < 16; i++) acc3[i] = 0.f;
#pragma unroll
            for (int ks = 0; ks < 8; ks++) {
                uint32_t a3[2][4], bf[2][2];
#pragma unroll
                for (int ms = 0; ms < 2; ms++)
                    LDSM4(a3[ms], aBase3 + (16 * ms * SH + 16 * ks) * 2);
#pragma unroll
                for (int nt = 0; nt < 2; nt++) {
                    const __half* bp = W3t + (wn3 + 8 * nt + g) * SH + 16 * ks + 2 * t;
                    bf[nt][0] = *(const uint32_t*)(bp);
                    bf[nt][1] = *(const uint32_t*)(bp + 8);
                }
#pragma unroll
                for (int ms = 0; ms < 2; ms++)
#pragma unroll
                    for (int nt = 0; nt < 2; nt++)
                        mma16816(&acc3[(ms * 2 + nt) * 4], a3[ms], bf[nt]);
            }
#pragma unroll
            for (int ms = 0; ms < 2; ms++)
#pragma unroll
                for (int nt = 0; nt < 2; nt++) {
                    int r  = wm3 + 16 * ms + g;
                    int c  = wn3 + 8 * nt + 2 * t;
                    int cp = c >> 1;
                    float* a = &acc3[(ms * 2 + nt) * 4];
                    float bb0 = b3s[c], bb1 = b3s[c + 1];
                    ztp[cp * ZSTH + r]     = packh2(a[0] + bb0, a[1] + bb1);
                    ztp[cp * ZSTH + r + 8] = packh2(a[2] + bb0, a[3] + bb1);
                }
        }
    };

    // prologue prefetch: slots 0,1 <- first pair
    {
        int bA = blockIdx.x;
        int bB = bA + grid; if (bB >= NB) bB = blockIdx.x;
        if (tid < 128) cp16(xraw + tid * 4, x + (size_t)bA * 512 + tid * 4);
        asm volatile("cp.async.commit_group;\n");
        if (tid < 128) cp16(xraw + 512 + tid * 4, x + (size_t)bB * 512 + tid * 4);
        asm volatile("cp.async.commit_group;\n");
    }

    int p = 0;
    for (int b = blockIdx.x; b < NB; b += 2 * grid, p ^= 1) {
        const int bA = b, bB = b + grid;
        const bool vB = bB < NB;
        // prefetch next pair into other-parity slots
        {
            int nA = b + 2 * grid; if (nA >= NB) nA = blockIdx.x;
            int nB = b + 3 * grid; if (nB >= NB) nB = blockIdx.x;
            int np = p ^ 1;
            if (tid < 128) cp16(xraw + (2 * np) * 512 + tid * 4, x + (size_t)nA * 512 + tid * 4);
            asm volatile("cp.async.commit_group;\n");
            if (tid < 128) cp16(xraw + (2 * np + 1) * 512 + tid * 4, x + (size_t)nB * 512 + tid * 4);
            asm volatile("cp.async.commit_group;\n");
        }
        asm volatile("cp.async.wait_group 2;\n");

        // eps prefetch: lane l<4 -> (batch A/A/B/B, latent 2w + (l&1))
        float ev = 0.f;
        if (lane < 4 && (lane < 2 || vB)) {
            int bb = (lane < 2) ? bA : bB;
            ev = eps[(size_t)bb * 16 + 2 * w + (lane & 1)];
        }
        __syncthreads();

        run_batch(xraw + (2 * p) * 512, zth);
        if (vB) {
            __syncthreads();
            run_batch(xraw + (2 * p + 1) * 512, zth + 16 * ZSTH);
        }
        __syncthreads();

        // ---- sort + pool: 4 half2 streams/warp (A: pair-rows 2w,2w+1; B: same) ----
        {
            uint32_t v[4][4];
#pragma unroll
            for (int ci = 0; ci < 4; ci++) {
                int row = (ci >> 1) * 16 + 2 * w + (ci & 1);
                uint4 q = *(const uint4*)&zth[row * ZSTH + 4 * lane];
                v[ci][0] = q.x; v[ci][1] = q.y; v[ci][2] = q.z; v[ci][3] = q.w;
            }
            // k=2
#pragma unroll
            for (int ci = 0; ci < 4; ci++) { CEXH(v[ci][0], v[ci][1], true); CEXH(v[ci][2], v[ci][3], false); }
            // k=4
            {
                const bool dsc = (lane & 1) == 0;
#pragma unroll
                for (int ci = 0; ci < 4; ci++) { CEXH(v[ci][0], v[ci][2], dsc); CEXH(v[ci][1], v[ci][3], dsc); }
#pragma unroll
                for (int ci = 0; ci < 4; ci++) { CEXH(v[ci][0], v[ci][1], dsc); CEXH(v[ci][2], v[ci][3], dsc); }
            }
            // k = 8..128
#pragma unroll
            for (int kk = 8; kk <= 128; kk <<= 1) {
                const bool dsc = (lane & (kk >> 2)) == 0;
#pragma unroll
                for (int d = kk >> 1; d >= 4; d >>= 1) {
                    const bool keep = dsc == ((lane & (d >> 2)) == 0);
#pragma unroll
                    for (int ci = 0; ci < 4; ci++)
#pragma unroll
                        for (int j = 0; j < 4; j++) {
                            uint32_t pv = __shfl_xor_sync(0xffffffffu, v[ci][j], d >> 2);
                            v[ci][j] = keep ? h2max(v[ci][j], pv) : h2min(v[ci][j], pv);
                        }
                }
#pragma unroll
                for (int ci = 0; ci < 4; ci++) { CEXH(v[ci][0], v[ci][2], dsc); CEXH(v[ci][1], v[ci][3], dsc); }
#pragma unroll
                for (int ci = 0; ci < 4; ci++) { CEXH(v[ci][0], v[ci][1], dsc); CEXH(v[ci][2], v[ci][3], dsc); }
            }
            // weighted pool (rank r = 4*lane+j); lo->mu, hi->logvar
            float s[8];
#pragma unroll
            for (int ci = 0; ci < 4; ci++) {
                float slo = 0.f, shi = 0.f;
#pragma unroll
                for (int j = 0; j < 4; j++) {
                    float2 f = __half22float2(*(__half2*)&v[ci][j]);
                    slo += f.x * wlo[ci & 1][j];
                    shi += f.y * whi[ci & 1][j];
                }
                s[2 * ci] = slo; s[2 * ci + 1] = shi;
            }
#pragma unroll
            for (int off = 16; off > 0; off >>= 1)
#pragma unroll
                for (int i = 0; i < 8; i++)
                    s[i] += __shfl_xor_sync(0xffffffffu, s[i], off);

            // outputs: lane l<4 -> (batch, latent 2w+(l&1))
            if (lane < 4 && (lane < 2 || vB)) {
                const int bb = (lane < 2) ? bA : bB;
                const int l  = 2 * w + (lane & 1);
                float mu = s[2 * lane];
                float lv = s[2 * lane + 1];
                float sp = mu + ev * expf(0.5f * lv);
                out[(size_t)bb * 16 + l]                       = mu;
                out[(size_t)NB * 16 + (size_t)bb * 16 + l]     = lv;
                out[(size_t)2 * NB * 16 + (size_t)bb * 16 + l] = sp;
            }
        }
        // no trailing barrier needed: next iteration's first zth write is
        // separated from these reads by the iteration-top __syncthreads()
    }
}

extern "C" void kernel_launch(void* const* d_in, const int* in_sizes, int n_in,
                              void* d_out, int out_size) {
    const float* x   = (const float*)d_in[0];
    const float* W1  = (const float*)d_in[1];
    const float* b1  = (const float*)d_in[2];
    const float* W2  = (const float*)d_in[3];
    const float* b2  = (const float*)d_in[4];
    const float* W3  = (const float*)d_in[5];
    const float* b3  = (const float*)d_in[6];
    const float* pw  = (const float*)d_in[7];
    const float* eps = (const float*)d_in[8];
    float* out = (float*)d_out;

    int dev = 0;
    cudaGetDevice(&dev);
    int nsm = 148;
    cudaDeviceGetAttribute(&nsm, cudaDevAttrMultiProcessorCount, dev);
    cudaFuncSetAttribute(enc_kernel, cudaFuncAttributeMaxDynamicSharedMemorySize, SMEM_BYTES);
    enc_kernel<<<nsm, 256, SMEM_BYTES>>>(x, W1, b1, W2, b2, W3, b3, pw, eps, out);
}

// round 7
// speedup vs baseline: 2.0863x; 1.0050x over previous
#include <cuda_runtime.h>
#include <cuda_fp16.h>
#include <cstdint>

#define NB    8192
#define SH    136    // padded half stride (68 words -> conflict-free)
#define ZSTH  136    // padded half2 stride for zth pair-rows

// shared memory byte offsets (16B aligned)
#define OFF_XRAW   0        // 4*512*4 = 8192 (4-slot ring)
#define OFF_B1     8192     // 512
#define OFF_B2     8704     // 512
#define OFF_B3     9216     // 128
#define OFF_W3T    9344     // 32*136*2 = 8704
#define OFF_H1A    18048    // 128*136*2 = 34816  (W2 staged here in prologue)
#define OFF_H1B    52864    // 34816
#define OFF_H2A    87680    // 34816
#define OFF_H2B    122496   // 34816
#define OFF_ZTH    157312   // 2*16*136*4 = 17408
#define SMEM_BYTES 174720

__device__ __forceinline__ void mma16816(float* d, const uint32_t* a, const uint32_t* b) {
    asm volatile(
        "mma.sync.aligned.m16n8k16.row.col.f32.f16.f16.f32 "
        "{%0,%1,%2,%3},{%4,%5,%6,%7},{%8,%9},{%0,%1,%2,%3};\n"
        : "+f"(d[0]), "+f"(d[1]), "+f"(d[2]), "+f"(d[3])
        : "r"(a[0]), "r"(a[1]), "r"(a[2]), "r"(a[3]), "r"(b[0]), "r"(b[1]));
}

__device__ __forceinline__ void mma16808(float* d, const uint32_t* a, uint32_t b) {
    asm volatile(
        "mma.sync.aligned.m16n8k8.row.col.f32.f16.f16.f32 "
        "{%0,%1,%2,%3},{%4,%5},{%6},{%0,%1,%2,%3};\n"
        : "+f"(d[0]), "+f"(d[1]), "+f"(d[2]), "+f"(d[3])
        : "r"(a[0]), "r"(a[1]), "r"(b));
}

#define LDSM4(r, addr) \
    asm volatile("ldmatrix.sync.aligned.m8n8.x4.shared.b16 {%0,%1,%2,%3}, [%4];" \
                 : "=r"((r)[0]), "=r"((r)[1]), "=r"((r)[2]), "=r"((r)[3]) : "r"(addr))

#define STSM4(addr, r0, r1, r2, r3) \
    asm volatile("stmatrix.sync.aligned.m8n8.x4.shared.b16 [%0], {%1,%2,%3,%4};" \
                 :: "r"(addr), "r"(r0), "r"(r1), "r"(r2), "r"(r3))

__device__ __forceinline__ void cp16(void* s, const void* g) {
    uint32_t sa = (uint32_t)__cvta_generic_to_shared(s);
    asm volatile("cp.async.ca.shared.global [%0], [%1], 16;\n" :: "r"(sa), "l"(g));
}

__device__ __forceinline__ uint32_t packh2(float a, float b) {
    __half2 h = __floats2half2_rn(a, b);
    return *(uint32_t*)&h;
}

__device__ __forceinline__ uint32_t h2max(uint32_t a, uint32_t b) {
    __half2 r = __hmax2(*(__half2*)&a, *(__half2*)&b);
    return *(uint32_t*)&r;
}
__device__ __forceinline__ uint32_t h2min(uint32_t a, uint32_t b) {
    __half2 r = __hmin2(*(__half2*)&a, *(__half2*)&b);
    return *(uint32_t*)&r;
}

#define CEXH(a, b, dsc) do { uint32_t _hi = h2max(a, b), _lo = h2min(a, b); \
                             (a) = (dsc) ? _hi : _lo; (b) = (dsc) ? _lo : _hi; } while (0)

__global__ void __launch_bounds__(256, 1)
enc_kernel(const float* __restrict__ x,  const float* __restrict__ W1,
           const float* __restrict__ b1, const float* __restrict__ W2,
           const float* __restrict__ b2, const float* __restrict__ W3,
           const float* __restrict__ b3, const float* __restrict__ pw,
           const float* __restrict__ eps, float* __restrict__ out) {
    extern __shared__ char smem[];
    float*    xraw  = (float*)(smem + OFF_XRAW);
    float*    b1s   = (float*)(smem + OFF_B1);
    float*    b2s   = (float*)(smem + OFF_B2);
    float*    b3s   = (float*)(smem + OFF_B3);
    __half*   W3t   = (__half*)(smem + OFF_W3T);
    uint32_t* zth   = (uint32_t*)(smem + OFF_ZTH);   // [2][16][ZSTH] half2

    const int tid  = threadIdx.x;
    const int w    = tid >> 5;
    const int lane = tid & 31;
    const int g    = lane >> 2, t = lane & 3;
    const int grid = gridDim.x;

    // warp tiles
    const int wm12 = (w & 1) * 64, wn12 = (w >> 1) * 32;   // layers 1,2: 64x32
    const int wm3  = (w & 3) * 32, wn3  = (w >> 2) * 16;   // layer 3: 32x16

    // ldmatrix / stmatrix lane address components
    const int mi    = lane >> 3;
    const int arow  = (mi & 1) * 8 + (lane & 7);
    const int acol  = (mi >> 1) * 8;

    const uint32_t smem_u32 = (uint32_t)__cvta_generic_to_shared(smem);
    // per-buffer base addresses (ldmatrix A / stmatrix C), offset by h1/h2 region
    const uint32_t aOff2 = ((wm12 + arow) * SH + acol) * 2;            // ldmatrix into L2
    const uint32_t aOff3 = ((wm3  + arow) * SH + acol) * 2;            // ldmatrix into L3
    const uint32_t sOff  = ((wm12 + arow) * SH + wn12 + acol) * 2;     // stmatrix from L1/L2

    // ---------------- prologue ----------------
    __half* W2t = (__half*)(smem + OFF_H1A);  // stage W2 in h1A region
    for (int i = tid; i < 16384; i += 256) {   // W2t[n][k] = W2[k][n]
        int k = i >> 7, n = i & 127;
        W2t[n * SH + k] = __float2half(W2[i]);
    }
    for (int i = tid; i < 4096; i += 256) {    // W3t[n][k] = W3[k][n]
        int k = i >> 5, n = i & 31;
        W3t[n * SH + k] = __float2half(W3[i]);
    }
    if (tid < 128) { b1s[tid] = b1[tid]; b2s[tid] = b2[tid]; }
    if (tid < 32)  b3s[tid] = b3[tid];
    __syncthreads();

    // persistent W2 fragments (64 regs/lane)
    uint32_t bW2[4][16];
#pragma unroll
    for (int nt = 0; nt < 4; nt++) {
        const __half* bp = W2t + (wn12 + 8 * nt + g) * SH + 2 * t;
#pragma unroll
        for (int ks = 0; ks < 8; ks++) {
            bW2[nt][2 * ks]     = *(const uint32_t*)(bp + 16 * ks);
            bW2[nt][2 * ks + 1] = *(const uint32_t*)(bp + 16 * ks + 8);
        }
    }
    // persistent W1 fragments
    uint32_t bW1[4];
#pragma unroll
    for (int nt = 0; nt < 4; nt++) {
        int n = wn12 + 8 * nt + g;
        bW1[nt] = (t < 2) ? packh2(W1[(2 * t) * 128 + n], W1[(2 * t + 1) * 128 + n]) : 0u;
    }
    // FSPool weights: stream parity q -> channels (4w+2q, 4w+2q+1)
    float wlo[2][4], whi[2][4];
#pragma unroll
    for (int q = 0; q < 2; q++) {
        int c0 = 4 * w + 2 * q;
#pragma unroll
        for (int j = 0; j < 4; j++) {
            int p = 4 * lane + j;
            float pos = (float)p * (20.0f / 127.0f);
            int idx = (int)pos; if (idx > 20) idx = 20;
            float frac = pos - (float)idx;
            int idx2 = idx + 1; if (idx2 > 20) idx2 = 20;
            wlo[q][j] = (1.0f - frac) * pw[c0 * 21 + idx]       + frac * pw[c0 * 21 + idx2];
            whi[q][j] = (1.0f - frac) * pw[(c0 + 1) * 21 + idx] + frac * pw[(c0 + 1) * 21 + idx2];
        }
    }

    // ---- phase lambdas (inlined; acc is per-call, peak regs unchanged) ----
    auto layer1 = [&](const float* xb, uint32_t h1Off) {
        float acc[64];
#pragma unroll
        for (int i = 0; i < 64; i++) acc[i] = 0.f;
        uint32_t a1[4][2];
#pragma unroll
        for (int ms = 0; ms < 4; ms++) {
            int row = wm12 + 16 * ms + g;
            if (t < 2) {
                float2 v0 = *(const float2*)&xb[row * 4 + 2 * t];
                float2 v1 = *(const float2*)&xb[(row + 8) * 4 + 2 * t];
                a1[ms][0] = packh2(v0.x, v0.y);
                a1[ms][1] = packh2(v1.x, v1.y);
            } else { a1[ms][0] = 0u; a1[ms][1] = 0u; }
        }
#pragma unroll
        for (int ms = 0; ms < 4; ms++)
#pragma unroll
            for (int nt = 0; nt < 4; nt++)
                mma16808(&acc[(ms * 4 + nt) * 4], a1[ms], bW1[nt]);
#pragma unroll
        for (int ms = 0; ms < 4; ms++)
#pragma unroll
            for (int nh = 0; nh < 2; nh++) {
                int c0 = wn12 + 16 * nh + 2 * t;
                float bb0 = b1s[c0], bb1 = b1s[c0 + 1];
                float bb2 = b1s[c0 + 8], bb3 = b1s[c0 + 9];
                float* aA = &acc[(ms * 4 + 2 * nh) * 4];
                float* aB = &acc[(ms * 4 + 2 * nh + 1) * 4];
                uint32_t p0 = packh2(fmaxf(aA[0] + bb0, 0.f), fmaxf(aA[1] + bb1, 0.f));
                uint32_t p1 = packh2(fmaxf(aA[2] + bb0, 0.f), fmaxf(aA[3] + bb1, 0.f));
                uint32_t p2 = packh2(fmaxf(aB[0] + bb2, 0.f), fmaxf(aB[1] + bb3, 0.f));
                uint32_t p3 = packh2(fmaxf(aB[2] + bb2, 0.f), fmaxf(aB[3] + bb3, 0.f));
                STSM4(h1Off + sOff + (16 * ms * SH + 16 * nh) * 2, p0, p1, p2, p3);
            }
    };

    auto layer2 = [&](uint32_t h1Off, uint32_t h2Off) {
        float acc[64];
#pragma unroll
        for (int i = 0; i < 64; i++) acc[i] = 0.f;
        uint32_t af[2][4][4];
        const uint32_t aB2 = h1Off + aOff2;
#pragma unroll
        for (int ms = 0; ms < 4; ms++) LDSM4(af[0][ms], aB2 + (16 * ms * SH) * 2);
#pragma unroll
        for (int ks = 0; ks < 8; ks++) {
            if (ks < 7) {
#pragma unroll
                for (int ms = 0; ms < 4; ms++)
                    LDSM4(af[(ks + 1) & 1][ms], aB2 + (16 * ms * SH + 16 * (ks + 1)) * 2);
            }
#pragma unroll
            for (int ms = 0; ms < 4; ms++)
#pragma unroll
                for (int nt = 0; nt < 4; nt++)
                    mma16816(&acc[(ms * 4 + nt) * 4], af[ks & 1][ms], &bW2[nt][2 * ks]);
        }
#pragma unroll
        for (int ms = 0; ms < 4; ms++)
#pragma unroll
            for (int nh = 0; nh < 2; nh++) {
                int c0 = wn12 + 16 * nh + 2 * t;
                float bb0 = b2s[c0], bb1 = b2s[c0 + 1];
                float bb2 = b2s[c0 + 8], bb3 = b2s[c0 + 9];
                float* aA = &acc[(ms * 4 + 2 * nh) * 4];
                float* aB = &acc[(ms * 4 + 2 * nh + 1) * 4];
                uint32_t p0 = packh2(fmaxf(aA[0] + bb0, 0.f), fmaxf(aA[1] + bb1, 0.f));
                uint32_t p1 = packh2(fmaxf(aA[2] + bb0, 0.f), fmaxf(aA[3] + bb1, 0.f));
                uint32_t p2 = packh2(fmaxf(aB[0] + bb2, 0.f), fmaxf(aB[1] + bb3, 0.f));
                uint32_t p3 = packh2(fmaxf(aB[2] + bb2, 0.f), fmaxf(aB[3] + bb3, 0.f));
                STSM4(h2Off + sOff + (16 * ms * SH + 16 * nh) * 2, p0, p1, p2, p3);
            }
    };

    auto layer3 = [&](uint32_t h2Off, uint32_t* ztp) {
        float acc3[16];
#pragma unroll
        for (int i = 0; i < 16; i++) acc3[i] = 0.f;
        const uint32_t aB3 = h2Off + aOff3;
#pragma unroll
        for (int ks = 0; ks < 8; ks++) {
            uint32_t a3[2][4], bf[2][2];
#pragma unroll
            for (int ms = 0; ms < 2; ms++)
                LDSM4(a3[ms], aB3 + (16 * ms * SH + 16 * ks) * 2);
#pragma unroll
            for (int nt = 0; nt < 2; nt++) {
                const __half* bp = W3t + (wn3 + 8 * nt + g) * SH + 16 * ks + 2 * t;
                bf[nt][0] = *(const uint32_t*)(bp);
                bf[nt][1] = *(const uint32_t*)(bp + 8);
            }
#pragma unroll
            for (int ms = 0; ms < 2; ms++)
#pragma unroll
                for (int nt = 0; nt < 2; nt++)
                    mma16816(&acc3[(ms * 2 + nt) * 4], a3[ms], bf[nt]);
        }
#pragma unroll
        for (int ms = 0; ms < 2; ms++)
#pragma unroll
            for (int nt = 0; nt < 2; nt++) {
                int r  = wm3 + 16 * ms + g;
                int c  = wn3 + 8 * nt + 2 * t;
                int cp = c >> 1;
                float* a = &acc3[(ms * 2 + nt) * 4];
                float bb0 = b3s[c], bb1 = b3s[c + 1];
                ztp[cp * ZSTH + r]     = packh2(a[0] + bb0, a[1] + bb1);
                ztp[cp * ZSTH + r + 8] = packh2(a[2] + bb0, a[3] + bb1);
            }
    };

    // prologue prefetch: slots 0,1 <- first pair
    {
        int bA = blockIdx.x;
        int bB = bA + grid; if (bB >= NB) bB = blockIdx.x;
        if (tid < 128) cp16(xraw + tid * 4, x + (size_t)bA * 512 + tid * 4);
        asm volatile("cp.async.commit_group;\n");
        if (tid < 128) cp16(xraw + 512 + tid * 4, x + (size_t)bB * 512 + tid * 4);
        asm volatile("cp.async.commit_group;\n");
    }

    int p = 0;
    for (int b = blockIdx.x; b < NB; b += 2 * grid, p ^= 1) {
        const int bA = b, bB = b + grid;
        const bool vB = bB < NB;
        // prefetch next pair into other-parity slots
        {
            int nA = b + 2 * grid; if (nA >= NB) nA = blockIdx.x;
            int nB = b + 3 * grid; if (nB >= NB) nB = blockIdx.x;
            int np = p ^ 1;
            if (tid < 128) cp16(xraw + (2 * np) * 512 + tid * 4, x + (size_t)nA * 512 + tid * 4);
            asm volatile("cp.async.commit_group;\n");
            if (tid < 128) cp16(xraw + (2 * np + 1) * 512 + tid * 4, x + (size_t)nB * 512 + tid * 4);
            asm volatile("cp.async.commit_group;\n");
        }
        asm volatile("cp.async.wait_group 2;\n");

        // eps prefetch: lane l<4 -> (batch A/A/B/B, latent 2w + (l&1))
        float ev = 0.f;
        if (lane < 4 && (lane < 2 || vB)) {
            int bb = (lane < 2) ? bA : bB;
            ev = eps[(size_t)bb * 16 + 2 * w + (lane & 1)];
        }
        __syncthreads();

        // ---- interleaved phases: A then B back-to-back, one barrier per phase ----
        layer1(xraw + (2 * p) * 512, OFF_H1A + smem_u32);
        if (vB) layer1(xraw + (2 * p + 1) * 512, OFF_H1B + smem_u32);
        __syncthreads();

        layer2(OFF_H1A + smem_u32, OFF_H2A + smem_u32);
        if (vB) layer2(OFF_H1B + smem_u32, OFF_H2B + smem_u32);
        __syncthreads();

        layer3(OFF_H2A + smem_u32, zth);
        if (vB) layer3(OFF_H2B + smem_u32, zth + 16 * ZSTH);
        __syncthreads();

        // ---- sort + pool: 4 half2 streams/warp (A: pair-rows 2w,2w+1; B: same) ----
        {
            uint32_t v[4][4];
#pragma unroll
            for (int ci = 0; ci < 4; ci++) {
                int row = (ci >> 1) * 16 + 2 * w + (ci & 1);
                uint4 q = *(const uint4*)&zth[row * ZSTH + 4 * lane];
                v[ci][0] = q.x; v[ci][1] = q.y; v[ci][2] = q.z; v[ci][3] = q.w;
            }
            // k=2
#pragma unroll
            for (int ci = 0; ci < 4; ci++) { CEXH(v[ci][0], v[ci][1], true); CEXH(v[ci][2], v[ci][3], false); }
            // k=4
            {
                const bool dsc = (lane & 1) == 0;
#pragma unroll
                for (int ci = 0; ci < 4; ci++) { CEXH(v[ci][0], v[ci][2], dsc); CEXH(v[ci][1], v[ci][3], dsc); }
#pragma unroll
                for (int ci = 0; ci < 4; ci++) { CEXH(v[ci][0], v[ci][1], dsc); CEXH(v[ci][2], v[ci][3], dsc); }
            }
            // k = 8..128
#pragma unroll
            for (int kk = 8; kk <= 128; kk <<= 1) {
                const bool dsc = (lane & (kk >> 2)) == 0;
#pragma unroll
                for (int d = kk >> 1; d >= 4; d >>= 1) {
                    const bool keep = dsc == ((lane & (d >> 2)) == 0);
#pragma unroll
                    for (int ci = 0; ci < 4; ci++)
#pragma unroll
                        for (int j = 0; j < 4; j++) {
                            uint32_t pv = __shfl_xor_sync(0xffffffffu, v[ci][j], d >> 2);
                            v[ci][j] = keep ? h2max(v[ci][j], pv) : h2min(v[ci][j], pv);
                        }
                }
#pragma unroll
                for (int ci = 0; ci < 4; ci++) { CEXH(v[ci][0], v[ci][2], dsc); CEXH(v[ci][1], v[ci][3], dsc); }
#pragma unroll
                for (int ci = 0; ci < 4; ci++) { CEXH(v[ci][0], v[ci][1], dsc); CEXH(v[ci][2], v[ci][3], dsc); }
            }
            // weighted pool (rank r = 4*lane+j); lo->mu, hi->logvar
            float s[8];
#pragma unroll
            for (int ci = 0; ci < 4; ci++) {
                float slo = 0.f, shi = 0.f;
#pragma unroll
                for (int j = 0; j < 4; j++) {
                    float2 f = __half22float2(*(__half2*)&v[ci][j]);
                    slo += f.x * wlo[ci & 1][j];
                    shi += f.y * whi[ci & 1][j];
                }
                s[2 * ci] = slo; s[2 * ci + 1] = shi;
            }
#pragma unroll
            for (int off = 16; off > 0; off >>= 1)
#pragma unroll
                for (int i = 0; i < 8; i++)
                    s[i] += __shfl_xor_sync(0xffffffffu, s[i], off);

            // outputs: lane l<4 -> (batch, latent 2w+(l&1))
            if (lane < 4 && (lane < 2 || vB)) {
                const int bb = (lane < 2) ? bA : bB;
                const int l  = 2 * w + (lane & 1);
                float mu = s[2 * lane];
                float lv = s[2 * lane + 1];
                float sp = mu + ev * expf(0.5f * lv);
                out[(size_t)bb * 16 + l]                       = mu;
                out[(size_t)NB * 16 + (size_t)bb * 16 + l]     = lv;
                out[(size_t)2 * NB * 16 + (size_t)bb * 16 + l] = sp;
            }
        }
        // next iteration's first zth write is separated from these reads by
        // the iteration-top __syncthreads() plus two more phase barriers
    }
}

extern "C" void kernel_launch(void* const* d_in, const int* in_sizes, int n_in,
                              void* d_out, int out_size) {
    const float* x   = (const float*)d_in[0];
    const float* W1  = (const float*)d_in[1];
    const float* b1  = (const float*)d_in[2];
    const float* W2  = (const float*)d_in[3];
    const float* b2  = (const float*)d_in[4];
    const float* W3  = (const float*)d_in[5];
    const float* b3  = (const float*)d_in[6];
    const float* pw  = (const float*)d_in[7];
    const float* eps = (const float*)d_in[8];
    float* out = (float*)d_out;

    int dev = 0;
    cudaGetDevice(&dev);
    int nsm = 148;
    cudaDeviceGetAttribute(&nsm, cudaDevAttrMultiProcessorCount, dev);
    cudaFuncSetAttribute(enc_kernel, cudaFuncAttributeMaxDynamicSharedMemorySize, SMEM_BYTES);
    enc_kernel<<<nsm, 256, SMEM_BYTES>>>(x, W1, b1, W2, b2, W3, b3, pw, eps, out);
}

// round 8
// speedup vs baseline: 2.0909x; 1.0022x over previous
#include <cuda_runtime.h>
#include <cuda_fp16.h>
#include <cstdint>

#define NB    8192
#define SH    136    // padded half stride (68 words -> conflict-free)
#define ZSTH  136    // padded half2 stride for zth pair-rows

// shared memory byte offsets (16B aligned)
#define OFF_XRAW   0        // 4*512*4 = 8192 (4-slot ring)
#define OFF_B1     8192     // 512
#define OFF_B2     8704     // 512
#define OFF_B3     9216     // 128
#define OFF_W3T    9344     // 32*136*2 = 8704
#define OFF_H1A    18048    // 128*136*2 = 34816  (W2 staged here in prologue)
#define OFF_H1B    52864    // 34816
#define OFF_H2A    87680    // 34816
#define OFF_H2B    122496   // 34816
#define OFF_ZTH    157312   // 2*16*136*4 = 17408
#define SMEM_BYTES 174720

#define NTHREADS 512   // 16 warps

__device__ __forceinline__ void mma16816(float* d, const uint32_t* a, const uint32_t* b) {
    asm volatile(
        "mma.sync.aligned.m16n8k16.row.col.f32.f16.f16.f32 "
        "{%0,%1,%2,%3},{%4,%5,%6,%7},{%8,%9},{%0,%1,%2,%3};\n"
        : "+f"(d[0]), "+f"(d[1]), "+f"(d[2]), "+f"(d[3])
        : "r"(a[0]), "r"(a[1]), "r"(a[2]), "r"(a[3]), "r"(b[0]), "r"(b[1]));
}

__device__ __forceinline__ void mma16808(float* d, const uint32_t* a, uint32_t b) {
    asm volatile(
        "mma.sync.aligned.m16n8k8.row.col.f32.f16.f16.f32 "
        "{%0,%1,%2,%3},{%4,%5},{%6},{%0,%1,%2,%3};\n"
        : "+f"(d[0]), "+f"(d[1]), "+f"(d[2]), "+f"(d[3])
        : "r"(a[0]), "r"(a[1]), "r"(b));
}

#define LDSM4(r, addr) \
    asm volatile("ldmatrix.sync.aligned.m8n8.x4.shared.b16 {%0,%1,%2,%3}, [%4];" \
                 : "=r"((r)[0]), "=r"((r)[1]), "=r"((r)[2]), "=r"((r)[3]) : "r"(addr))

#define STSM4(addr, r0, r1, r2, r3) \
    asm volatile("stmatrix.sync.aligned.m8n8.x4.shared.b16 [%0], {%1,%2,%3,%4};" \
                 :: "r"(addr), "r"(r0), "r"(r1), "r"(r2), "r"(r3))

__device__ __forceinline__ void cp16(void* s, const void* g) {
    uint32_t sa = (uint32_t)__cvta_generic_to_shared(s);
    asm volatile("cp.async.ca.shared.global [%0], [%1], 16;\n" :: "r"(sa), "l"(g));
}

__device__ __forceinline__ uint32_t packh2(float a, float b) {
    __half2 h = __floats2half2_rn(a, b);
    return *(uint32_t*)&h;
}

__device__ __forceinline__ uint32_t h2max(uint32_t a, uint32_t b) {
    __half2 r = __hmax2(*(__half2*)&a, *(__half2*)&b);
    return *(uint32_t*)&r;
}
__device__ __forceinline__ uint32_t h2min(uint32_t a, uint32_t b) {
    __half2 r = __hmin2(*(__half2*)&a, *(__half2*)&b);
    return *(uint32_t*)&r;
}

#define CEXH(a, b, dsc) do { uint32_t _hi = h2max(a, b), _lo = h2min(a, b); \
                             (a) = (dsc) ? _hi : _lo; (b) = (dsc) ? _lo : _hi; } while (0)

__global__ void __launch_bounds__(NTHREADS, 1)
enc_kernel(const float* __restrict__ x,  const float* __restrict__ W1,
           const float* __restrict__ b1, const float* __restrict__ W2,
           const float* __restrict__ b2, const float* __restrict__ W3,
           const float* __restrict__ b3, const float* __restrict__ pw,
           const float* __restrict__ eps, float* __restrict__ out) {
    extern __shared__ char smem[];
    float*    xraw  = (float*)(smem + OFF_XRAW);
    float*    b1s   = (float*)(smem + OFF_B1);
    float*    b2s   = (float*)(smem + OFF_B2);
    float*    b3s   = (float*)(smem + OFF_B3);
    __half*   W3t   = (__half*)(smem + OFF_W3T);
    uint32_t* zth   = (uint32_t*)(smem + OFF_ZTH);   // [2][16][ZSTH] half2

    const int tid  = threadIdx.x;
    const int w    = tid >> 5;
    const int lane = tid & 31;
    const int g    = lane >> 2, t = lane & 3;
    const int grid = gridDim.x;

    // warp tiles (16 warps)
    const int wm12 = (w & 1) * 64, wn12 = (w >> 1) * 16;   // layers 1,2: 64x16
    const int wm3  = (w & 7) * 16, wn3  = (w >> 3) * 16;   // layer 3: 16x16

    // ldmatrix / stmatrix lane address components
    const int mi    = lane >> 3;
    const int arow  = (mi & 1) * 8 + (lane & 7);
    const int acol  = (mi >> 1) * 8;

    const uint32_t smem_u32 = (uint32_t)__cvta_generic_to_shared(smem);
    const uint32_t aOff2 = ((wm12 + arow) * SH + acol) * 2;            // ldmatrix for L2 (M=64)
    const uint32_t aOff3 = ((wm3  + arow) * SH + acol) * 2;            // ldmatrix for L3 (M=16)
    const uint32_t sOff  = ((wm12 + arow) * SH + wn12 + acol) * 2;     // stmatrix for L1/L2

    // ---------------- prologue ----------------
    __half* W2t = (__half*)(smem + OFF_H1A);  // stage W2 in h1A region
    for (int i = tid; i < 16384; i += NTHREADS) {   // W2t[n][k] = W2[k][n]
        int k = i >> 7, n = i & 127;
        W2t[n * SH + k] = __float2half(W2[i]);
    }
    for (int i = tid; i < 4096; i += NTHREADS) {    // W3t[n][k] = W3[k][n]
        int k = i >> 5, n = i & 31;
        W3t[n * SH + k] = __float2half(W3[i]);
    }
    if (tid < 128) { b1s[tid] = b1[tid]; b2s[tid] = b2[tid]; }
    if (tid < 32)  b3s[tid] = b3[tid];
    __syncthreads();

    // persistent W2 fragments (32 regs/lane: N=16 tile)
    uint32_t bW2[2][16];
#pragma unroll
    for (int nt = 0; nt < 2; nt++) {
        const __half* bp = W2t + (wn12 + 8 * nt + g) * SH + 2 * t;
#pragma unroll
        for (int ks = 0; ks < 8; ks++) {
            bW2[nt][2 * ks]     = *(const uint32_t*)(bp + 16 * ks);
            bW2[nt][2 * ks + 1] = *(const uint32_t*)(bp + 16 * ks + 8);
        }
    }
    // persistent W1 fragments
    uint32_t bW1[2];
#pragma unroll
    for (int nt = 0; nt < 2; nt++) {
        int n = wn12 + 8 * nt + g;
        bW1[nt] = (t < 2) ? packh2(W1[(2 * t) * 128 + n], W1[(2 * t + 1) * 128 + n]) : 0u;
    }
    // FSPool weights: warp sorts streams q=0,1 -> channels (4(w&7)+2q, +1)
    float wlo[2][4], whi[2][4];
#pragma unroll
    for (int q = 0; q < 2; q++) {
        int c0 = 4 * (w & 7) + 2 * q;
#pragma unroll
        for (int j = 0; j < 4; j++) {
            int p = 4 * lane + j;
            float pos = (float)p * (20.0f / 127.0f);
            int idx = (int)pos; if (idx > 20) idx = 20;
            float frac = pos - (float)idx;
            int idx2 = idx + 1; if (idx2 > 20) idx2 = 20;
            wlo[q][j] = (1.0f - frac) * pw[c0 * 21 + idx]       + frac * pw[c0 * 21 + idx2];
            whi[q][j] = (1.0f - frac) * pw[(c0 + 1) * 21 + idx] + frac * pw[(c0 + 1) * 21 + idx2];
        }
    }

    // ---- phase lambdas ----
    auto layer1 = [&](const float* xb, uint32_t h1Off) {
        float acc[32];
#pragma unroll
        for (int i = 0; i < 32; i++) acc[i] = 0.f;
        uint32_t a1[4][2];
#pragma unroll
        for (int ms = 0; ms < 4; ms++) {
            int row = wm12 + 16 * ms + g;
            if (t < 2) {
                float2 v0 = *(const float2*)&xb[row * 4 + 2 * t];
                float2 v1 = *(const float2*)&xb[(row + 8) * 4 + 2 * t];
                a1[ms][0] = packh2(v0.x, v0.y);
                a1[ms][1] = packh2(v1.x, v1.y);
            } else { a1[ms][0] = 0u; a1[ms][1] = 0u; }
        }
#pragma unroll
        for (int ms = 0; ms < 4; ms++)
#pragma unroll
            for (int nt = 0; nt < 2; nt++)
                mma16808(&acc[(ms * 2 + nt) * 4], a1[ms], bW1[nt]);
#pragma unroll
        for (int ms = 0; ms < 4; ms++) {
            int c0 = wn12 + 2 * t;
            float bb0 = b1s[c0], bb1 = b1s[c0 + 1];
            float bb2 = b1s[c0 + 8], bb3 = b1s[c0 + 9];
            float* aA = &acc[(ms * 2 + 0) * 4];
            float* aB = &acc[(ms * 2 + 1) * 4];
            uint32_t p0 = packh2(fmaxf(aA[0] + bb0, 0.f), fmaxf(aA[1] + bb1, 0.f));
            uint32_t p1 = packh2(fmaxf(aA[2] + bb0, 0.f), fmaxf(aA[3] + bb1, 0.f));
            uint32_t p2 = packh2(fmaxf(aB[0] + bb2, 0.f), fmaxf(aB[1] + bb3, 0.f));
            uint32_t p3 = packh2(fmaxf(aB[2] + bb2, 0.f), fmaxf(aB[3] + bb3, 0.f));
            STSM4(h1Off + sOff + (16 * ms * SH) * 2, p0, p1, p2, p3);
        }
    };

    auto layer2 = [&](uint32_t h1Off, uint32_t h2Off) {
        float acc[32];
#pragma unroll
        for (int i = 0; i < 32; i++) acc[i] = 0.f;
        const uint32_t aB2 = h1Off + aOff2;
#pragma unroll
        for (int ks = 0; ks < 8; ks++) {
            uint32_t af[4][4];
#pragma unroll
            for (int ms = 0; ms < 4; ms++)
                LDSM4(af[ms], aB2 + (16 * ms * SH + 16 * ks) * 2);
#pragma unroll
            for (int ms = 0; ms < 4; ms++)
#pragma unroll
                for (int nt = 0; nt < 2; nt++)
                    mma16816(&acc[(ms * 2 + nt) * 4], af[ms], &bW2[nt][2 * ks]);
        }
#pragma unroll
        for (int ms = 0; ms < 4; ms++) {
            int c0 = wn12 + 2 * t;
            float bb0 = b2s[c0], bb1 = b2s[c0 + 1];
            float bb2 = b2s[c0 + 8], bb3 = b2s[c0 + 9];
            float* aA = &acc[(ms * 2 + 0) * 4];
            float* aB = &acc[(ms * 2 + 1) * 4];
            uint32_t p0 = packh2(fmaxf(aA[0] + bb0, 0.f), fmaxf(aA[1] + bb1, 0.f));
            uint32_t p1 = packh2(fmaxf(aA[2] + bb0, 0.f), fmaxf(aA[3] + bb1, 0.f));
            uint32_t p2 = packh2(fmaxf(aB[0] + bb2, 0.f), fmaxf(aB[1] + bb3, 0.f));
            uint32_t p3 = packh2(fmaxf(aB[2] + bb2, 0.f), fmaxf(aB[3] + bb3, 0.f));
            STSM4(h2Off + sOff + (16 * ms * SH) * 2, p0, p1, p2, p3);
        }
    };

    auto layer3 = [&](uint32_t h2Off, uint32_t* ztp) {
        float acc3[8];
#pragma unroll
        for (int i = 0; i < 8; i++) acc3[i] = 0.f;
        const uint32_t aB3 = h2Off + aOff3;
#pragma unroll
        for (int ks = 0; ks < 8; ks++) {
            uint32_t a3[4], bf[2][2];
            LDSM4(a3, aB3 + (16 * ks) * 2);
#pragma unroll
            for (int nt = 0; nt < 2; nt++) {
                const __half* bp = W3t + (wn3 + 8 * nt + g) * SH + 16 * ks + 2 * t;
                bf[nt][0] = *(const uint32_t*)(bp);
                bf[nt][1] = *(const uint32_t*)(bp + 8);
            }
#pragma unroll
            for (int nt = 0; nt < 2; nt++)
                mma16816(&acc3[nt * 4], a3, bf[nt]);
        }
#pragma unroll
        for (int nt = 0; nt < 2; nt++) {
            int r  = wm3 + g;
            int c  = wn3 + 8 * nt + 2 * t;
            int cp = c >> 1;
            float* a = &acc3[nt * 4];
            float bb0 = b3s[c], bb1 = b3s[c + 1];
            ztp[cp * ZSTH + r]     = packh2(a[0] + bb0, a[1] + bb1);
            ztp[cp * ZSTH + r + 8] = packh2(a[2] + bb0, a[3] + bb1);
        }
    };

    // prologue prefetch: slots 0,1 <- first pair
    {
        int bA = blockIdx.x;
        int bB = bA + grid; if (bB >= NB) bB = blockIdx.x;
        if (tid < 128) cp16(xraw + tid * 4, x + (size_t)bA * 512 + tid * 4);
        asm volatile("cp.async.commit_group;\n");
        if (tid < 128) cp16(xraw + 512 + tid * 4, x + (size_t)bB * 512 + tid * 4);
        asm volatile("cp.async.commit_group;\n");
    }

    int p = 0;
    for (int b = blockIdx.x; b < NB; b += 2 * grid, p ^= 1) {
        const int bA = b, bB = b + grid;
        const bool vB = bB < NB;
        // prefetch next pair into other-parity slots
        {
            int nA = b + 2 * grid; if (nA >= NB) nA = blockIdx.x;
            int nB = b + 3 * grid; if (nB >= NB) nB = blockIdx.x;
            int np = p ^ 1;
            if (tid < 128) cp16(xraw + (2 * np) * 512 + tid * 4, x + (size_t)nA * 512 + tid * 4);
            asm volatile("cp.async.commit_group;\n");
            if (tid < 128) cp16(xraw + (2 * np + 1) * 512 + tid * 4, x + (size_t)nB * 512 + tid * 4);
            asm volatile("cp.async.commit_group;\n");
        }
        asm volatile("cp.async.wait_group 2;\n");

        // eps prefetch: warp w handles batch w>>3, latents l = 2(w&7)+q, lane q<2
        const int wb = w >> 3;
        const bool wvalid = (wb == 0) || vB;
        float ev = 0.f;
        if (lane < 2 && wvalid) {
            int bb = wb ? bB : bA;
            ev = eps[(size_t)bb * 16 + 2 * (w & 7) + lane];
        }
        __syncthreads();

        // ---- interleaved phases: A then B back-to-back, one barrier per phase ----
        layer1(xraw + (2 * p) * 512, OFF_H1A + smem_u32);
        if (vB) layer1(xraw + (2 * p + 1) * 512, OFF_H1B + smem_u32);
        __syncthreads();

        layer2(OFF_H1A + smem_u32, OFF_H2A + smem_u32);
        if (vB) layer2(OFF_H1B + smem_u32, OFF_H2B + smem_u32);
        __syncthreads();

        layer3(OFF_H2A + smem_u32, zth);
        if (vB) layer3(OFF_H2B + smem_u32, zth + 16 * ZSTH);
        __syncthreads();

        // ---- sort + pool: 2 half2 streams/warp; warp w -> batch w>>3, rows 2(w&7)+q ----
        {
            const int sr = wb * 16 + 2 * (w & 7);
            uint32_t v[2][4];
#pragma unroll
            for (int q = 0; q < 2; q++) {
                uint4 qd = *(const uint4*)&zth[(sr + q) * ZSTH + 4 * lane];
                v[q][0] = qd.x; v[q][1] = qd.y; v[q][2] = qd.z; v[q][3] = qd.w;
            }
            // k=2
#pragma unroll
            for (int q = 0; q < 2; q++) { CEXH(v[q][0], v[q][1], true); CEXH(v[q][2], v[q][3], false); }
            // k=4
            {
                const bool dsc = (lane & 1) == 0;
#pragma unroll
                for (int q = 0; q < 2; q++) { CEXH(v[q][0], v[q][2], dsc); CEXH(v[q][1], v[q][3], dsc); }
#pragma unroll
                for (int q = 0; q < 2; q++) { CEXH(v[q][0], v[q][1], dsc); CEXH(v[q][2], v[q][3], dsc); }
            }
            // k = 8..128
#pragma unroll
            for (int kk = 8; kk <= 128; kk <<= 1) {
                const bool dsc = (lane & (kk >> 2)) == 0;
#pragma unroll
                for (int d = kk >> 1; d >= 4; d >>= 1) {
                    const bool keep = dsc == ((lane & (d >> 2)) == 0);
#pragma unroll
                    for (int q = 0; q < 2; q++)
#pragma unroll
                        for (int j = 0; j < 4; j++) {
                            uint32_t pv = __shfl_xor_sync(0xffffffffu, v[q][j], d >> 2);
                            v[q][j] = keep ? h2max(v[q][j], pv) : h2min(v[q][j], pv);
                        }
                }
#pragma unroll
                for (int q = 0; q < 2; q++) { CEXH(v[q][0], v[q][2], dsc); CEXH(v[q][1], v[q][3], dsc); }
#pragma unroll
                for (int q = 0; q < 2; q++) { CEXH(v[q][0], v[q][1], dsc); CEXH(v[q][2], v[q][3], dsc); }
            }
            // weighted pool (rank r = 4*lane+j); lo->mu, hi->logvar
            float s[4];
#pragma unroll
            for (int q = 0; q < 2; q++) {
                float slo = 0.f, shi = 0.f;
#pragma unroll
                for (int j = 0; j < 4; j++) {
                    float2 f = __half22float2(*(__half2*)&v[q][j]);
                    slo += f.x * wlo[q][j];
                    shi += f.y * whi[q][j];
                }
                s[2 * q] = slo; s[2 * q + 1] = shi;
            }
#pragma unroll
            for (int off = 16; off > 0; off >>= 1)
#pragma unroll
                for (int i = 0; i < 4; i++)
                    s[i] += __shfl_xor_sync(0xffffffffu, s[i], off);

            // outputs: lane q<2 -> latent 2(w&7)+q of batch wb
            if (lane < 2 && wvalid) {
                const int bb = wb ? bB : bA;
                const int l  = 2 * (w & 7) + lane;
                float mu = s[2 * lane];
                float lv = s[2 * lane + 1];
                float sp = mu + ev * expf(0.5f * lv);
                out[(size_t)bb * 16 + l]                       = mu;
                out[(size_t)NB * 16 + (size_t)bb * 16 + l]     = lv;
                out[(size_t)2 * NB * 16 + (size_t)bb * 16 + l] = sp;
            }
        }
        // next iteration's first zth write is separated from these reads by
        // the iteration-top __syncthreads() plus two more phase barriers
    }
}

extern "C" void kernel_launch(void* const* d_in, const int* in_sizes, int n_in,
                              void* d_out, int out_size) {
    const float* x   = (const float*)d_in[0];
    const float* W1  = (const float*)d_in[1];
    const float* b1  = (const float*)d_in[2];
    const float* W2  = (const float*)d_in[3];
    const float* b2  = (const float*)d_in[4];
    const float* W3  = (const float*)d_in[5];
    const float* b3  = (const float*)d_in[6];
    const float* pw  = (const float*)d_in[7];
    const float* eps = (const float*)d_in[8];
    float* out = (float*)d_out;

    int dev = 0;
    cudaGetDevice(&dev);
    int nsm = 148;
    cudaDeviceGetAttribute(&nsm, cudaDevAttrMultiProcessorCount, dev);
    cudaFuncSetAttribute(enc_kernel, cudaFuncAttributeMaxDynamicSharedMemorySize, SMEM_BYTES);
    enc_kernel<<<nsm, NTHREADS, SMEM_BYTES>>>(x, W1, b1, W2, b2, W3, b3, pw, eps, out);
}